// round 5
// baseline (speedup 1.0000x reference)
#include <cuda_runtime.h>

#define BH     16       // b*h
#define HEADS  8
#define NSEQ   8192
#define DH     64
#define MLAND  256
#define MMSZ   (MLAND*MLAND)   // 65536
#define SPLITS 4

// ---------------- device scratch ----------------
__device__ float g_qland[BH*MLAND*DH];
__device__ float g_kland[BH*MLAND*DH];
__device__ float g_mm[6ll*BH*MMSZ];                 // X, A, T, V, ZA, ZB
__device__ float g_p3v[BH*MLAND*DH];                // softmax(sim3) @ v (combined)
__device__ float g_p3vp[(size_t)SPLITS*BH*MLAND*DH];// split partials
__device__ float g_mlp[(size_t)SPLITS*BH*MLAND*2];  // split (m, l)
__device__ float g_W[BH*MLAND*DH];                  // attn2_inv @ p3v
__device__ int   g_maxcs, g_maxrs;

#define IX  0
#define IA  1
#define IT  2
#define IV  3
#define IZA 4
#define IZB 5

// ---------------- kernel 1: landmarks ----------------
__global__ void k_landmarks(const float* __restrict__ q, const float* __restrict__ k) {
    int m = blockIdx.x, bh = blockIdx.y;
    const float* src = blockIdx.z ? k : q;
    float* dst = blockIdx.z ? g_kland : g_qland;
    int j = threadIdx.x;  // 64
    const float* p = src + ((size_t)bh*NSEQ + (size_t)m*32)*DH + j;
    float s = 0.f;
#pragma unroll
    for (int r = 0; r < 32; r++) s += p[r*DH];
    dst[(bh*MLAND + m)*DH + j] = s * (1.f/32.f);
    if (blockIdx.z == 0 && m == 0 && bh == 0 && j == 0) { g_maxcs = 0; g_maxrs = 0; }
}

// ---------------- kernel 2: attn2 = softmax(q_land @ k_land^T) ----------------
#define SMEM_ATTN2 ((256*68 + 32*68)*4)
__global__ void k_attn2() {
    extern __shared__ float sm[];
    float* kl = sm;               // 256 x 68
    float* ql = sm + 256*68;      // 32 x 68
    int bh = blockIdx.y, r0 = blockIdx.x*32, t = threadIdx.x;
    const float4* ks = (const float4*)(g_kland + (size_t)bh*MLAND*DH);
    for (int i = t; i < 256*16; i += 256) { int row=i>>4, c=i&15; *(float4*)(kl+row*68+c*4) = ks[row*16+c]; }
    const float4* qs = (const float4*)(g_qland + ((size_t)bh*MLAND + r0)*DH);
    for (int i = t; i < 32*16; i += 256)  { int row=i>>4, c=i&15; *(float4*)(ql+row*68+c*4) = qs[row*16+c]; }
    __syncthreads();
    int r = t >> 3, j8 = t & 7;
    float acc[32];
#pragma unroll
    for (int c = 0; c < 32; c++) acc[c] = 0.f;
    for (int kk = 0; kk < 64; kk += 4) {
        float4 qv = *(float4*)(ql + r*68 + kk);
#pragma unroll
        for (int c = 0; c < 32; c++) {
            float4 kv = *(float4*)(kl + (j8 + 8*c)*68 + kk);
            acc[c] += qv.x*kv.x + qv.y*kv.y + qv.z*kv.z + qv.w*kv.w;
        }
    }
    float mx = -1e30f;
#pragma unroll
    for (int c = 0; c < 32; c++) mx = fmaxf(mx, acc[c]);
#pragma unroll
    for (int o = 4; o; o >>= 1) mx = fmaxf(mx, __shfl_xor_sync(0xffffffffu, mx, o, 8));
    float sum = 0.f;
#pragma unroll
    for (int c = 0; c < 32; c++) { acc[c] = __expf(acc[c] - mx); sum += acc[c]; }
#pragma unroll
    for (int o = 4; o; o >>= 1) sum += __shfl_xor_sync(0xffffffffu, sum, o, 8);
    float inv = 1.f / sum;
    float* X = g_mm + (size_t)IX*BH*MMSZ + (size_t)bh*MMSZ + (size_t)(r0 + r)*MLAND;
#pragma unroll
    for (int c = 0; c < 32; c++) X[j8 + 8*c] = acc[c] * inv;
}

// ---------------- kernel 3: global max col-sum / row-sum of attn2 ----------------
__global__ void k_colrow() {
    int bh = blockIdx.x, t = threadIdx.x;
    const float* x = g_mm + (size_t)IX*BH*MMSZ + (size_t)bh*MMSZ;
    float cs = 0.f, rs = 0.f;
    for (int i = 0; i < 256; i++) cs += x[i*256 + t];
    for (int j = 0; j < 256; j++) rs += x[t*256 + j];
#pragma unroll
    for (int o = 16; o; o >>= 1) {
        cs = fmaxf(cs, __shfl_xor_sync(0xffffffffu, cs, o));
        rs = fmaxf(rs, __shfl_xor_sync(0xffffffffu, rs, o));
    }
    __shared__ float sc[8], sr[8];
    if ((t & 31) == 0) { sc[t>>5] = cs; sr[t>>5] = rs; }
    __syncthreads();
    if (t == 0) {
        float mc = sc[0], mr = sr[0];
        for (int w = 1; w < 8; w++) { mc = fmaxf(mc, sc[w]); mr = fmaxf(mr, sr[w]); }
        atomicMax(&g_maxcs, __float_as_int(mc));
        atomicMax(&g_maxrs, __float_as_int(mr));
    }
}

// ================= double-buffered 64x64 SGEMM core =================
// Out = alpha*P + beta*(P@Q) + diag*I   (P:[256,256], Q/Out:[256,NQ])
template<int NQ>
__global__ void k_gemm2(const float* __restrict__ Pg, const float* __restrict__ Qg,
                        float* __restrict__ Og, float alpha, float beta, float diag) {
    __shared__ float sA[2][16][68];
    __shared__ float sB[2][16][68];
    int bh = blockIdx.z;
    const float* P = Pg + (size_t)bh*MMSZ;
    const float* Q = Qg + (size_t)bh*256*NQ;
    float*       O = Og + (size_t)bh*256*NQ;
    int i0 = blockIdx.y*64, j0 = blockIdx.x*64;
    int t = threadIdx.x, tx = t & 15, ty = t >> 4;
    int la_i = t >> 2, la_k = (t & 3)*4;
    int lb_k = t >> 4, lb_j = (t & 15)*4;
    const float* pA = P + (size_t)(i0 + la_i)*256 + la_k;
    const float* pB = Q + (size_t)lb_k*NQ + j0 + lb_j;
    float4 av = *(const float4*)pA;
    float4 bv = *(const float4*)pB;
    sA[0][la_k  ][la_i] = av.x; sA[0][la_k+1][la_i] = av.y;
    sA[0][la_k+2][la_i] = av.z; sA[0][la_k+3][la_i] = av.w;
    *(float4*)&sB[0][lb_k][lb_j] = bv;
    __syncthreads();
    float acc[4][4];
#pragma unroll
    for (int a = 0; a < 4; a++)
#pragma unroll
        for (int b = 0; b < 4; b++) acc[a][b] = 0.f;
    for (int s = 0; s < 16; s++) {
        int cur = s & 1;
        if (s < 15) {
            av = *(const float4*)(pA + (s+1)*16);
            bv = *(const float4*)(pB + (size_t)(s+1)*16*NQ);
        }
#pragma unroll
        for (int k = 0; k < 16; k++) {
            float4 a = *(float4*)&sA[cur][k][ty*4];
            float4 b = *(float4*)&sB[cur][k][tx*4];
            float ar[4] = {a.x,a.y,a.z,a.w}, br[4] = {b.x,b.y,b.z,b.w};
#pragma unroll
            for (int ii = 0; ii < 4; ii++)
#pragma unroll
                for (int jj = 0; jj < 4; jj++) acc[ii][jj] += ar[ii]*br[jj];
        }
        if (s < 15) {
            int nxt = cur ^ 1;
            sA[nxt][la_k  ][la_i] = av.x; sA[nxt][la_k+1][la_i] = av.y;
            sA[nxt][la_k+2][la_i] = av.z; sA[nxt][la_k+3][la_i] = av.w;
            *(float4*)&sB[nxt][lb_k][lb_j] = bv;
            __syncthreads();
        }
    }
#pragma unroll
    for (int ii = 0; ii < 4; ii++) {
        int i = i0 + ty*4 + ii;
        float o[4];
#pragma unroll
        for (int jj = 0; jj < 4; jj++) o[jj] = beta*acc[ii][jj];
        if (alpha != 0.f) {
            float4 pv = *(const float4*)(P + (size_t)i*256 + j0 + tx*4);
            o[0] += alpha*pv.x; o[1] += alpha*pv.y; o[2] += alpha*pv.z; o[3] += alpha*pv.w;
        }
        if (diag != 0.f) {
#pragma unroll
            for (int jj = 0; jj < 4; jj++) if (i == j0 + tx*4 + jj) o[jj] += diag;
        }
        *(float4*)(O + (size_t)i*NQ + j0 + tx*4) = make_float4(o[0], o[1], o[2], o[3]);
    }
}

// A = s * (X @ X^T)
__global__ void k_gemm_xxt(const float* __restrict__ Xg, float* __restrict__ Og) {
    __shared__ float sA[2][16][68];
    __shared__ float sB[2][16][68];
    float s = 1.f / (__int_as_float(g_maxcs) * __int_as_float(g_maxrs));
    int bh = blockIdx.z;
    const float* X = Xg + (size_t)bh*MMSZ;
    float*       O = Og + (size_t)bh*MMSZ;
    int i0 = blockIdx.y*64, j0 = blockIdx.x*64;
    int t = threadIdx.x, tx = t & 15, ty = t >> 4;
    int la_i = t >> 2, la_k = (t & 3)*4;
    const float* pA = X + (size_t)(i0 + la_i)*256 + la_k;
    const float* pB = X + (size_t)(j0 + la_i)*256 + la_k;
    float4 av = *(const float4*)pA;
    float4 bv = *(const float4*)pB;
    sA[0][la_k][la_i]=av.x; sA[0][la_k+1][la_i]=av.y; sA[0][la_k+2][la_i]=av.z; sA[0][la_k+3][la_i]=av.w;
    sB[0][la_k][la_i]=bv.x; sB[0][la_k+1][la_i]=bv.y; sB[0][la_k+2][la_i]=bv.z; sB[0][la_k+3][la_i]=bv.w;
    __syncthreads();
    float acc[4][4];
#pragma unroll
    for (int a = 0; a < 4; a++)
#pragma unroll
        for (int b = 0; b < 4; b++) acc[a][b] = 0.f;
    for (int st = 0; st < 16; st++) {
        int cur = st & 1;
        if (st < 15) { av = *(const float4*)(pA + (st+1)*16); bv = *(const float4*)(pB + (st+1)*16); }
#pragma unroll
        for (int k = 0; k < 16; k++) {
            float4 a = *(float4*)&sA[cur][k][ty*4];
            float4 b = *(float4*)&sB[cur][k][tx*4];
            float ar[4] = {a.x,a.y,a.z,a.w}, br[4] = {b.x,b.y,b.z,b.w};
#pragma unroll
            for (int ii = 0; ii < 4; ii++)
#pragma unroll
                for (int jj = 0; jj < 4; jj++) acc[ii][jj] += ar[ii]*br[jj];
        }
        if (st < 15) {
            int nxt = cur ^ 1;
            sA[nxt][la_k][la_i]=av.x; sA[nxt][la_k+1][la_i]=av.y; sA[nxt][la_k+2][la_i]=av.z; sA[nxt][la_k+3][la_i]=av.w;
            sB[nxt][la_k][la_i]=bv.x; sB[nxt][la_k+1][la_i]=bv.y; sB[nxt][la_k+2][la_i]=bv.z; sB[nxt][la_k+3][la_i]=bv.w;
            __syncthreads();
        }
    }
#pragma unroll
    for (int ii = 0; ii < 4; ii++) {
        int i = i0 + ty*4 + ii;
        *(float4*)(O + (size_t)i*256 + j0 + tx*4) =
            make_float4(s*acc[ii][0], s*acc[ii][1], s*acc[ii][2], s*acc[ii][3]);
    }
}

// Out = s * (X^T @ V)
__global__ void k_gemm_atx(const float* __restrict__ Xg, const float* __restrict__ Vg,
                           float* __restrict__ Og) {
    __shared__ float sA[2][16][68];
    __shared__ float sB[2][16][68];
    float s = 1.f / (__int_as_float(g_maxcs) * __int_as_float(g_maxrs));
    int bh = blockIdx.z;
    const float* X = Xg + (size_t)bh*MMSZ;
    const float* V = Vg + (size_t)bh*MMSZ;
    float*       O = Og + (size_t)bh*MMSZ;
    int i0 = blockIdx.y*64, j0 = blockIdx.x*64;
    int t = threadIdx.x, tx = t & 15, ty = t >> 4;
    int ka = t >> 4, ia = (t & 15)*4;
    int lb_k = t >> 4, lb_j = (t & 15)*4;
    const float* pA = X + (size_t)ka*256 + i0 + ia;
    const float* pB = V + (size_t)lb_k*256 + j0 + lb_j;
    float4 av = *(const float4*)pA;
    float4 bv = *(const float4*)pB;
    *(float4*)&sA[0][ka][ia] = av;
    *(float4*)&sB[0][lb_k][lb_j] = bv;
    __syncthreads();
    float acc[4][4];
#pragma unroll
    for (int a = 0; a < 4; a++)
#pragma unroll
        for (int b = 0; b < 4; b++) acc[a][b] = 0.f;
    for (int st = 0; st < 16; st++) {
        int cur = st & 1;
        if (st < 15) {
            av = *(const float4*)(pA + (size_t)(st+1)*16*256);
            bv = *(const float4*)(pB + (size_t)(st+1)*16*256);
        }
#pragma unroll
        for (int k = 0; k < 16; k++) {
            float4 a = *(float4*)&sA[cur][k][ty*4];
            float4 b = *(float4*)&sB[cur][k][tx*4];
            float ar[4] = {a.x,a.y,a.z,a.w}, br[4] = {b.x,b.y,b.z,b.w};
#pragma unroll
            for (int ii = 0; ii < 4; ii++)
#pragma unroll
                for (int jj = 0; jj < 4; jj++) acc[ii][jj] += ar[ii]*br[jj];
        }
        if (st < 15) {
            int nxt = cur ^ 1;
            *(float4*)&sA[nxt][ka][ia] = av;
            *(float4*)&sB[nxt][lb_k][lb_j] = bv;
            __syncthreads();
        }
    }
#pragma unroll
    for (int ii = 0; ii < 4; ii++) {
        int i = i0 + ty*4 + ii;
        *(float4*)(O + (size_t)i*256 + j0 + tx*4) =
            make_float4(s*acc[ii][0], s*acc[ii][1], s*acc[ii][2], s*acc[ii][3]);
    }
}

// ---------------- attn3v: split-KV flash, gemm-style tiles ----------------
#define SMEM_A3V (4*64*68*4)
__global__ void k_attn3v(const float* __restrict__ k, const float* __restrict__ v) {
    extern __shared__ float sm[];
    float* sQt = sm;            // [64 d][68] rows
    float* sKt = sm + 64*68;    // [64 d][68] cols
    float* sV  = sm + 2*64*68;  // [64 seq][68 d]
    float* sP  = sm + 3*64*68;  // [64 seq][68 rows]
    int bh = blockIdx.z, m0 = blockIdx.x*64, sp = blockIdx.y;
    int t = threadIdx.x, tx = t & 15, ty = t >> 4;
    for (int i = t; i < 64*16; i += 256) {
        int row = i >> 4, c = i & 15;
        float4 qv = *(const float4*)(g_qland + ((size_t)bh*MLAND + m0 + row)*DH + c*4);
        sQt[(c*4+0)*68 + row] = qv.x; sQt[(c*4+1)*68 + row] = qv.y;
        sQt[(c*4+2)*68 + row] = qv.z; sQt[(c*4+3)*68 + row] = qv.w;
    }
    float m_run[4], l_run[4], acc[4][4];
#pragma unroll
    for (int i = 0; i < 4; i++) {
        m_run[i] = -1e30f; l_run[i] = 0.f;
#pragma unroll
        for (int j = 0; j < 4; j++) acc[i][j] = 0.f;
    }
    const float* kb = k + (size_t)bh*NSEQ*DH;
    const float* vb = v + (size_t)bh*NSEQ*DH;
    int n0base = sp * (NSEQ/SPLITS);
    __syncthreads();
    for (int c0 = 0; c0 < NSEQ/SPLITS; c0 += 64) {
        int n0 = n0base + c0;
        for (int i = t; i < 64*16; i += 256) {
            int row = i >> 4, cc = i & 15;
            float4 kv = *(const float4*)(kb + (size_t)(n0+row)*DH + cc*4);
            sKt[(cc*4+0)*68 + row] = kv.x; sKt[(cc*4+1)*68 + row] = kv.y;
            sKt[(cc*4+2)*68 + row] = kv.z; sKt[(cc*4+3)*68 + row] = kv.w;
            *(float4*)(sV + row*68 + cc*4) = *(const float4*)(vb + (size_t)(n0+row)*DH + cc*4);
        }
        __syncthreads();
        float s4[4][4];
#pragma unroll
        for (int i = 0; i < 4; i++)
#pragma unroll
            for (int j = 0; j < 4; j++) s4[i][j] = 0.f;
        for (int d = 0; d < 64; d++) {
            float4 qv = *(float4*)(sQt + d*68 + ty*4);
            float4 kv = *(float4*)(sKt + d*68 + tx*4);
            float qr[4] = {qv.x,qv.y,qv.z,qv.w}, kr[4] = {kv.x,kv.y,kv.z,kv.w};
#pragma unroll
            for (int i = 0; i < 4; i++)
#pragma unroll
                for (int j = 0; j < 4; j++) s4[i][j] += qr[i]*kr[j];
        }
#pragma unroll
        for (int i = 0; i < 4; i++) {
            float mx = fmaxf(fmaxf(s4[i][0], s4[i][1]), fmaxf(s4[i][2], s4[i][3]));
#pragma unroll
            for (int o = 8; o; o >>= 1) mx = fmaxf(mx, __shfl_xor_sync(0xffffffffu, mx, o, 16));
            float mn = fmaxf(m_run[i], mx);
            float corr = __expf(m_run[i] - mn);
            m_run[i] = mn;
            float ls = 0.f;
#pragma unroll
            for (int j = 0; j < 4; j++) { s4[i][j] = __expf(s4[i][j] - mn); ls += s4[i][j]; }
#pragma unroll
            for (int o = 8; o; o >>= 1) ls += __shfl_xor_sync(0xffffffffu, ls, o, 16);
            l_run[i] = l_run[i]*corr + ls;
#pragma unroll
            for (int j = 0; j < 4; j++) acc[i][j] *= corr;
        }
#pragma unroll
        for (int j = 0; j < 4; j++)
            *(float4*)(sP + (tx*4+j)*68 + ty*4) = make_float4(s4[0][j], s4[1][j], s4[2][j], s4[3][j]);
        __syncthreads();
        for (int kk = 0; kk < 64; kk++) {
            float4 pv = *(float4*)(sP + kk*68 + ty*4);
            float4 vv = *(float4*)(sV + kk*68 + tx*4);
            float pr[4] = {pv.x,pv.y,pv.z,pv.w}, vr[4] = {vv.x,vv.y,vv.z,vv.w};
#pragma unroll
            for (int i = 0; i < 4; i++)
#pragma unroll
                for (int j = 0; j < 4; j++) acc[i][j] += pr[i]*vr[j];
        }
        __syncthreads();
    }
    float* outp = g_p3vp + (((size_t)sp*BH + bh)*MLAND + m0)*DH;
#pragma unroll
    for (int i = 0; i < 4; i++)
        *(float4*)(outp + (size_t)(ty*4+i)*DH + tx*4) =
            make_float4(acc[i][0], acc[i][1], acc[i][2], acc[i][3]);
    if (tx == 0) {
#pragma unroll
        for (int i = 0; i < 4; i++) {
            size_t mi = (((size_t)sp*BH + bh)*MLAND + m0 + ty*4 + i)*2;
            g_mlp[mi] = m_run[i]; g_mlp[mi+1] = l_run[i];
        }
    }
}

__global__ void k_combine() {
    int row = blockIdx.x, bh = blockIdx.y, d = threadIdx.x;
    float m[SPLITS], l[SPLITS];
#pragma unroll
    for (int s = 0; s < SPLITS; s++) {
        size_t mi = (((size_t)s*BH + bh)*MLAND + row)*2;
        m[s] = g_mlp[mi]; l[s] = g_mlp[mi+1];
    }
    float M = m[0];
#pragma unroll
    for (int s = 1; s < SPLITS; s++) M = fmaxf(M, m[s]);
    float L = 0.f, o = 0.f;
#pragma unroll
    for (int s = 0; s < SPLITS; s++) {
        float w = __expf(m[s] - M);
        L += l[s]*w;
        o += g_p3vp[(((size_t)s*BH + bh)*MLAND + row)*DH + d] * w;
    }
    g_p3v[((size_t)bh*MLAND + row)*DH + d] = o / L;
}

// ---------------- fused1: out = softmax(q @ k_land^T) @ W + conv(v) ----------------
#define SMEM_F1 ((256*68 + 32*68 + 32*264)*4)
__global__ void k_fused1(const float* __restrict__ q, const float* __restrict__ v,
                         const float* __restrict__ cw, float* __restrict__ out) {
    extern __shared__ float sm[];
    float* kl = sm;
    float* ql = sm + 256*68;
    float* ss = sm + 256*68 + 32*68;
    int bh = blockIdx.y, g0 = blockIdx.x*32, t = threadIdx.x;
    int r = t >> 3, j8 = t & 7;
    const float4* ksrc = (const float4*)(g_kland + (size_t)bh*MLAND*DH);
    for (int i = t; i < 256*16; i += 256) { int row=i>>4, c=i&15; *(float4*)(kl+row*68+c*4) = ksrc[row*16+c]; }
    const float4* qsrc = (const float4*)(q + ((size_t)bh*NSEQ + g0)*DH);
    for (int i = t; i < 32*16; i += 256)  { int row=i>>4, c=i&15; *(float4*)(ql+row*68+c*4) = qsrc[row*16+c]; }
    __syncthreads();
    float acc[32];
#pragma unroll
    for (int c = 0; c < 32; c++) acc[c] = 0.f;
    for (int kk = 0; kk < 64; kk += 4) {
        float4 qv = *(float4*)(ql + r*68 + kk);
#pragma unroll
        for (int c = 0; c < 32; c++) {
            float4 kv = *(float4*)(kl + (j8 + 8*c)*68 + kk);
            acc[c] += qv.x*kv.x + qv.y*kv.y + qv.z*kv.z + qv.w*kv.w;
        }
    }
    float mx = -1e30f;
#pragma unroll
    for (int c = 0; c < 32; c++) mx = fmaxf(mx, acc[c]);
#pragma unroll
    for (int o = 4; o; o >>= 1) mx = fmaxf(mx, __shfl_xor_sync(0xffffffffu, mx, o, 8));
    float sum = 0.f;
#pragma unroll
    for (int c = 0; c < 32; c++) { acc[c] = __expf(acc[c] - mx); sum += acc[c]; }
#pragma unroll
    for (int o = 4; o; o >>= 1) sum += __shfl_xor_sync(0xffffffffu, sum, o, 8);
    float inv = 1.f / sum;
#pragma unroll
    for (int c = 0; c < 32; c++) ss[r*264 + j8 + 8*c] = acc[c] * inv;
    __syncthreads();
    const float4* wsrc = (const float4*)(g_W + (size_t)bh*MLAND*DH);
    for (int i = t; i < 256*16; i += 256) { int row=i>>4, c=i&15; *(float4*)(kl+row*68+c*4) = wsrc[row*16+c]; }
    __syncthreads();
    float oacc[8];
#pragma unroll
    for (int c = 0; c < 8; c++) oacc[c] = 0.f;
    int col = j8*8;
    const float* srow = ss + r*264;
    for (int kk = 0; kk < 256; kk += 4) {
        float4 p4 = *(float4*)(srow + kk);
        float pk[4] = {p4.x, p4.y, p4.z, p4.w};
#pragma unroll
        for (int u = 0; u < 4; u++) {
            float4 w0 = *(float4*)(kl + (kk+u)*68 + col);
            float4 w1 = *(float4*)(kl + (kk+u)*68 + col + 4);
            oacc[0] += pk[u]*w0.x; oacc[1] += pk[u]*w0.y; oacc[2] += pk[u]*w0.z; oacc[3] += pk[u]*w0.w;
            oacc[4] += pk[u]*w1.x; oacc[5] += pk[u]*w1.y; oacc[6] += pk[u]*w1.z; oacc[7] += pk[u]*w1.w;
        }
    }
    __syncthreads();
    const float* vb = v + (size_t)bh*NSEQ*DH;
    for (int i = t; i < 64*16; i += 256) {
        int row = i >> 4, c = i & 15, gr = g0 - 16 + row;
        float4 val = make_float4(0.f, 0.f, 0.f, 0.f);
        if (gr >= 0 && gr < NSEQ) val = *(const float4*)(vb + (size_t)gr*DH + c*4);
        *(float4*)(kl + row*68 + c*4) = val;
    }
    if (t < 33) ql[t] = cw[(bh & 7)*33 + t];
    __syncthreads();
    float res[8];
#pragma unroll
    for (int c = 0; c < 8; c++) res[c] = 0.f;
#pragma unroll
    for (int tt = 0; tt < 33; tt++) {
        float w = ql[tt];
        float4 v0 = *(float4*)(kl + (r + tt)*68 + col);
        float4 v1 = *(float4*)(kl + (r + tt)*68 + col + 4);
        res[0] += w*v0.x; res[1] += w*v0.y; res[2] += w*v0.z; res[3] += w*v0.w;
        res[4] += w*v1.x; res[5] += w*v1.y; res[6] += w*v1.z; res[7] += w*v1.w;
    }
    float* ob = out + ((size_t)bh*NSEQ + g0 + r)*DH + col;
    *(float4*)ob       = make_float4(oacc[0]+res[0], oacc[1]+res[1], oacc[2]+res[2], oacc[3]+res[3]);
    *(float4*)(ob + 4) = make_float4(oacc[4]+res[4], oacc[5]+res[5], oacc[6]+res[6], oacc[7]+res[7]);
}

// ---------------- launcher ----------------
extern "C" void kernel_launch(void* const* d_in, const int* in_sizes, int n_in,
                              void* d_out, int out_size) {
    (void)in_sizes; (void)n_in; (void)out_size;
    const float* q  = (const float*)d_in[0];
    const float* k  = (const float*)d_in[1];
    const float* v  = (const float*)d_in[2];
    const float* cw = (const float*)d_in[3];
    float* out = (float*)d_out;

    cudaFuncSetAttribute(k_attn2,  cudaFuncAttributeMaxDynamicSharedMemorySize, SMEM_ATTN2);
    cudaFuncSetAttribute(k_attn3v, cudaFuncAttributeMaxDynamicSharedMemorySize, SMEM_A3V);
    cudaFuncSetAttribute(k_fused1, cudaFuncAttributeMaxDynamicSharedMemorySize, SMEM_F1);

    float *mm, *p3v, *W;
    cudaGetSymbolAddress((void**)&mm,  g_mm);
    cudaGetSymbolAddress((void**)&p3v, g_p3v);
    cudaGetSymbolAddress((void**)&W,   g_W);

    const size_t S = (size_t)BH * MMSZ;
    float *X = mm + IX*S, *A = mm + IA*S, *T = mm + IT*S;
    float *V = mm + IV*S, *ZA = mm + IZA*S, *ZB = mm + IZB*S;

    k_landmarks<<<dim3(MLAND, BH, 2), 64>>>(q, k);
    k_attn2<<<dim3(8, BH), 256, SMEM_ATTN2>>>();
    k_colrow<<<BH, 256>>>();

    dim3 gg(4, 4, BH);
    // iteration 1 (z0 = s*X^T folded into transposed GEMMs)
    k_gemm_xxt<<<gg, 256>>>(X, A);                                   // A  = s*X@X^T
    k_gemm2<256><<<gg, 256>>>(A, A, T, 7.f, -1.f, 0.f);              // T  = 7A - A@A
    k_gemm2<256><<<gg, 256>>>(A, T, V, -3.75f, 0.25f, 3.25f);        // V  = 3.25I - 3.75A + .25A@T
    k_gemm_atx<<<gg, 256>>>(X, V, ZA);                               // z1 = s*X^T@V
    float *zi = ZA, *zo = ZB;
    for (int it = 1; it < 6; it++) {
        k_gemm2<256><<<gg, 256>>>(X,  zi, A, 0.f, 1.f, 0.f);
        k_gemm2<256><<<gg, 256>>>(A,  A,  T, 7.f, -1.f, 0.f);
        k_gemm2<256><<<gg, 256>>>(A,  T,  V, -3.75f, 0.25f, 3.25f);
        k_gemm2<256><<<gg, 256>>>(zi, V,  zo, 0.f, 1.f, 0.f);
        float* tmp = zi; zi = zo; zo = tmp;
    }

    k_attn3v<<<dim3(4, SPLITS, BH), 256, SMEM_A3V>>>(k, v);
    k_combine<<<dim3(MLAND, BH), 64>>>();
    k_gemm2<64><<<dim3(1, 4, BH), 256>>>(zi, p3v, W, 0.f, 1.f, 0.f);  // W = z@p3v
    k_fused1<<<dim3(256, BH), 256, SMEM_F1>>>(q, v, cw, out);
}

// round 9
// speedup vs baseline: 1.0309x; 1.0309x over previous
#include <cuda_runtime.h>
#include <cstdint>

#define BH     16
#define NSEQ   8192
#define DH     64
#define MLAND  256
#define MMSZ   (MLAND*MLAND)
#define SPLITS 4

// fp32 matrix pool slots
#define PX   0
#define PXT  1
#define PA   2
#define PAT  3
#define PTT  4
#define PVT  5
#define PZ0  6
#define PZ0T 7
#define PZ1  8
#define PZ1T 9
__device__ float g_pool[10ll*BH*MMSZ];
__device__ float g_qland[BH*MLAND*DH];
__device__ float g_kland[BH*MLAND*DH];
__device__ float g_p3v[BH*MLAND*DH];
__device__ float g_p3vp[(size_t)SPLITS*BH*MLAND*DH];
__device__ float g_mlp[(size_t)SPLITS*BH*MLAND*2];
__device__ float g_W[BH*MLAND*DH];
__device__ int   g_maxcs, g_maxrs;

__device__ __forceinline__ float tf32r(float x) {
    uint32_t u;
    asm("cvt.rna.tf32.f32 %0, %1;" : "=r"(u) : "f"(x));
    return __uint_as_float(u);
}
#define MMA_TF32(c, a0, a1, a2, a3, b0, b1) \
    asm volatile("mma.sync.aligned.m16n8k8.row.col.f32.tf32.tf32.f32 " \
        "{%0,%1,%2,%3}, {%4,%5,%6,%7}, {%8,%9}, {%0,%1,%2,%3};" \
        : "+f"((c)[0]), "+f"((c)[1]), "+f"((c)[2]), "+f"((c)[3]) \
        : "r"(a0), "r"(a1), "r"(a2), "r"(a3), "r"(b0), "r"(b1))

// ---------- kernel 1: landmarks ----------
__global__ void k_landmarks(const float* __restrict__ q, const float* __restrict__ k) {
    int m = blockIdx.x, bh = blockIdx.y;
    const float* src = blockIdx.z ? k : q;
    float* dst = blockIdx.z ? g_kland : g_qland;
    int j = threadIdx.x;
    const float* p = src + ((size_t)bh*NSEQ + (size_t)m*32)*DH + j;
    float s = 0.f;
#pragma unroll
    for (int r = 0; r < 32; r++) s += p[r*DH];
    dst[(bh*MLAND + m)*DH + j] = s * (1.f/32.f);
    if (blockIdx.z == 0 && m == 0 && bh == 0 && j == 0) { g_maxcs = 0; g_maxrs = 0; }
}

// ---------- kernel 2: attn2 -> X, XT (fp32) ----------
#define SMEM_ATTN2 ((256*68 + 32*68)*4)
__global__ void k_attn2() {
    extern __shared__ float sm[];
    float* kl = sm;
    float* ql = sm + 256*68;
    int bh = blockIdx.y, r0 = blockIdx.x*32, t = threadIdx.x;
    const float4* ks = (const float4*)(g_kland + (size_t)bh*MLAND*DH);
    for (int i = t; i < 256*16; i += 256) { int row=i>>4, c=i&15; *(float4*)(kl+row*68+c*4) = ks[row*16+c]; }
    const float4* qs = (const float4*)(g_qland + ((size_t)bh*MLAND + r0)*DH);
    for (int i = t; i < 32*16; i += 256)  { int row=i>>4, c=i&15; *(float4*)(ql+row*68+c*4) = qs[row*16+c]; }
    __syncthreads();
    int r = t >> 3, j8 = t & 7;
    float acc[32];
#pragma unroll
    for (int c = 0; c < 32; c++) acc[c] = 0.f;
    for (int kk = 0; kk < 64; kk += 4) {
        float4 qv = *(float4*)(ql + r*68 + kk);
#pragma unroll
        for (int c = 0; c < 32; c++) {
            float4 kv = *(float4*)(kl + (j8 + 8*c)*68 + kk);
            acc[c] += qv.x*kv.x + qv.y*kv.y + qv.z*kv.z + qv.w*kv.w;
        }
    }
    float mx = -1e30f;
#pragma unroll
    for (int c = 0; c < 32; c++) mx = fmaxf(mx, acc[c]);
#pragma unroll
    for (int o = 4; o; o >>= 1) mx = fmaxf(mx, __shfl_xor_sync(0xffffffffu, mx, o, 8));
    float sum = 0.f;
#pragma unroll
    for (int c = 0; c < 32; c++) { acc[c] = __expf(acc[c] - mx); sum += acc[c]; }
#pragma unroll
    for (int o = 4; o; o >>= 1) sum += __shfl_xor_sync(0xffffffffu, sum, o, 8);
    float inv = 1.f / sum;
    int row = r0 + r;
    float* X  = g_pool + ((size_t)PX*BH + bh)*MMSZ;
    float* XT = g_pool + ((size_t)PXT*BH + bh)*MMSZ;
#pragma unroll
    for (int c = 0; c < 32; c++) {
        float vv = acc[c] * inv;
        int col = j8 + 8*c;
        X[(size_t)row*MLAND + col] = vv;
        XT[(size_t)col*MLAND + row] = vv;
    }
}

// ---------- kernel 3: max col/row sums ----------
__global__ void k_colrow() {
    int bh = blockIdx.x, t = threadIdx.x;
    const float* x = g_pool + ((size_t)PX*BH + bh)*MMSZ;
    float cs = 0.f, rs = 0.f;
    for (int i = 0; i < 256; i++) cs += x[i*256 + t];
    for (int j = 0; j < 256; j++) rs += x[t*256 + j];
#pragma unroll
    for (int o = 16; o; o >>= 1) {
        cs = fmaxf(cs, __shfl_xor_sync(0xffffffffu, cs, o));
        rs = fmaxf(rs, __shfl_xor_sync(0xffffffffu, rs, o));
    }
    __shared__ float sc[8], sr[8];
    if ((t & 31) == 0) { sc[t>>5] = cs; sr[t>>5] = rs; }
    __syncthreads();
    if (t == 0) {
        float mc = sc[0], mr = sr[0];
        for (int w = 1; w < 8; w++) { mc = fmaxf(mc, sc[w]); mr = fmaxf(mr, sr[w]); }
        atomicMax(&g_maxcs, __float_as_int(mc));
        atomicMax(&g_maxrs, __float_as_int(mr));
    }
}

// ---------- tf32 tensor-core GEMM: C = alpha*P + beta*(A @ Bop^T) + diag*I ----------
// A, Bop, P, C, CT: [256][256] fp32 K-major rows. Writes C rows and/or CT where non-null.
// grid (4, 2, BH): block 128 rows x 64 cols, 256 thr = 8 warps (4M x 2N), warp 32x32.
__global__ void __launch_bounds__(256, 1) k_tmma32(
    const float* __restrict__ Ag, const float* __restrict__ Bg, const float* __restrict__ Pg,
    float* __restrict__ Cg, float* __restrict__ CTg,
    float alpha, float beta, float diag, int scaled)
{
    __shared__ __align__(16) float sA[2][128][20];
    __shared__ __align__(16) float sB[2][64][20];
    int bh = blockIdx.z;
    int row0 = blockIdx.y*128, col0 = blockIdx.x*64;
    int t = threadIdx.x, lane = t & 31, w = t >> 5;
    int wm = w >> 1, wn = w & 1;
    int gid = lane >> 2, tig = lane & 3;
    const float* Ab = Ag + (size_t)bh*MMSZ;
    const float* Bb = Bg + (size_t)bh*MMSZ;
    int lr = t >> 1, lh = t & 1;
    const float* gA = Ab + (size_t)(row0 + lr)*MLAND + lh*8;
    const float* gB = Bb + (size_t)(col0 + (lr & 63))*MLAND + lh*8;
    bool doB = (t < 128);

    float4 av0 = *(const float4*)gA;
    float4 av1 = *(const float4*)(gA + 4);
    float4 bv0 = make_float4(0,0,0,0), bv1 = make_float4(0,0,0,0);
    if (doB) { bv0 = *(const float4*)gB; bv1 = *(const float4*)(gB + 4); }

    auto stage = [&](int buf, float4 a0, float4 a1, float4 b0, float4 b1) {
        float4 ca0 = make_float4(tf32r(a0.x), tf32r(a0.y), tf32r(a0.z), tf32r(a0.w));
        float4 ca1 = make_float4(tf32r(a1.x), tf32r(a1.y), tf32r(a1.z), tf32r(a1.w));
        *(float4*)&sA[buf][lr][lh*8]     = ca0;
        *(float4*)&sA[buf][lr][lh*8 + 4] = ca1;
        if (doB) {
            float4 cb0 = make_float4(tf32r(b0.x), tf32r(b0.y), tf32r(b0.z), tf32r(b0.w));
            float4 cb1 = make_float4(tf32r(b1.x), tf32r(b1.y), tf32r(b1.z), tf32r(b1.w));
            *(float4*)&sB[buf][lr & 63][lh*8]     = cb0;
            *(float4*)&sB[buf][lr & 63][lh*8 + 4] = cb1;
        }
    };
    stage(0, av0, av1, bv0, bv1);
    __syncthreads();

    float acc[2][4][4];
#pragma unroll
    for (int i = 0; i < 2; i++)
#pragma unroll
        for (int j = 0; j < 4; j++)
#pragma unroll
            for (int c = 0; c < 4; c++) acc[i][j][c] = 0.f;

    for (int ks = 0; ks < 16; ks++) {
        int cur = ks & 1;
        if (ks < 15) {
            av0 = *(const float4*)(gA + (ks+1)*16);
            av1 = *(const float4*)(gA + (ks+1)*16 + 4);
            if (doB) {
                bv0 = *(const float4*)(gB + (ks+1)*16);
                bv1 = *(const float4*)(gB + (ks+1)*16 + 4);
            }
        }
#pragma unroll
        for (int kh = 0; kh < 2; kh++) {
            int kb = kh*8 + tig;
            uint32_t af[2][4], bfr[4][2];
#pragma unroll
            for (int mt = 0; mt < 2; mt++) {
                int rr = wm*32 + mt*16 + gid;
                af[mt][0] = __float_as_uint(sA[cur][rr    ][kb]);
                af[mt][1] = __float_as_uint(sA[cur][rr + 8][kb]);
                af[mt][2] = __float_as_uint(sA[cur][rr    ][kb + 4]);
                af[mt][3] = __float_as_uint(sA[cur][rr + 8][kb + 4]);
            }
#pragma unroll
            for (int nt = 0; nt < 4; nt++) {
                int cc = wn*32 + nt*8 + gid;
                bfr[nt][0] = __float_as_uint(sB[cur][cc][kb]);
                bfr[nt][1] = __float_as_uint(sB[cur][cc][kb + 4]);
            }
#pragma unroll
            for (int mt = 0; mt < 2; mt++)
#pragma unroll
                for (int nt = 0; nt < 4; nt++)
                    MMA_TF32(acc[mt][nt], af[mt][0], af[mt][1], af[mt][2], af[mt][3],
                             bfr[nt][0], bfr[nt][1]);
        }
        if (ks < 15) {
            stage(cur ^ 1, av0, av1, bv0, bv1);
            __syncthreads();
        }
    }

    float be = beta;
    if (scaled) be *= 1.f / (__int_as_float(g_maxcs) * __int_as_float(g_maxrs));
    const float* Pb = Pg ? Pg + (size_t)bh*MMSZ : (const float*)0;
    float* Cp  = Cg  ? Cg  + (size_t)bh*MMSZ : (float*)0;
    float* CTp = CTg ? CTg + (size_t)bh*MMSZ : (float*)0;
#pragma unroll
    for (int mt = 0; mt < 2; mt++)
#pragma unroll
        for (int nt = 0; nt < 4; nt++) {
            int gcol = col0 + wn*32 + nt*8 + 2*tig;
#pragma unroll
            for (int half = 0; half < 2; half++) {
                int grow = row0 + wm*32 + mt*16 + gid + half*8;
                float o0 = be * acc[mt][nt][2*half + 0];
                float o1 = be * acc[mt][nt][2*half + 1];
                if (Pb) {
                    float2 pv = *(const float2*)(Pb + (size_t)grow*MLAND + gcol);
                    o0 += alpha * pv.x;
                    o1 += alpha * pv.y;
                }
                if (diag != 0.f) {
                    if (grow == gcol)     o0 += diag;
                    if (grow == gcol + 1) o1 += diag;
                }
                if (Cp) *(float2*)(Cp + (size_t)grow*MLAND + gcol) = make_float2(o0, o1);
                if (CTp) {
                    CTp[(size_t)gcol*MLAND + grow]       = o0;
                    CTp[(size_t)(gcol+1)*MLAND + grow]   = o1;
                }
            }
        }
}

// ---------- fp32 double-buffered SGEMM (iters 5,6 + W) ----------
template<int NQ>
__global__ void k_gemm2(const float* __restrict__ Pg, const float* __restrict__ Qg,
                        float* __restrict__ Og, float alpha, float beta, float diag) {
    __shared__ float sA[2][16][68];
    __shared__ float sB[2][16][68];
    int bh = blockIdx.z;
    const float* P = Pg + (size_t)bh*MMSZ;
    const float* Q = Qg + (size_t)bh*256*NQ;
    float*       O = Og + (size_t)bh*256*NQ;
    int i0 = blockIdx.y*64, j0 = blockIdx.x*64;
    int t = threadIdx.x, tx = t & 15, ty = t >> 4;
    int la_i = t >> 2, la_k = (t & 3)*4;
    int lb_k = t >> 4, lb_j = (t & 15)*4;
    const float* pA = P + (size_t)(i0 + la_i)*256 + la_k;
    const float* pB = Q + (size_t)lb_k*NQ + j0 + lb_j;
    float4 av = *(const float4*)pA;
    float4 bv = *(const float4*)pB;
    sA[0][la_k  ][la_i] = av.x; sA[0][la_k+1][la_i] = av.y;
    sA[0][la_k+2][la_i] = av.z; sA[0][la_k+3][la_i] = av.w;
    *(float4*)&sB[0][lb_k][lb_j] = bv;
    __syncthreads();
    float acc[4][4];
#pragma unroll
    for (int a = 0; a < 4; a++)
#pragma unroll
        for (int b = 0; b < 4; b++) acc[a][b] = 0.f;
    for (int s = 0; s < 16; s++) {
        int cur = s & 1;
        if (s < 15) {
            av = *(const float4*)(pA + (s+1)*16);
            bv = *(const float4*)(pB + (size_t)(s+1)*16*NQ);
        }
#pragma unroll
        for (int k = 0; k < 16; k++) {
            float4 a = *(float4*)&sA[cur][k][ty*4];
            float4 b = *(float4*)&sB[cur][k][tx*4];
            float ar[4] = {a.x,a.y,a.z,a.w}, br[4] = {b.x,b.y,b.z,b.w};
#pragma unroll
            for (int ii = 0; ii < 4; ii++)
#pragma unroll
                for (int jj = 0; jj < 4; jj++) acc[ii][jj] += ar[ii]*br[jj];
        }
        if (s < 15) {
            int nxt = cur ^ 1;
            sA[nxt][la_k  ][la_i] = av.x; sA[nxt][la_k+1][la_i] = av.y;
            sA[nxt][la_k+2][la_i] = av.z; sA[nxt][la_k+3][la_i] = av.w;
            *(float4*)&sB[nxt][lb_k][lb_j] = bv;
            __syncthreads();
        }
    }
#pragma unroll
    for (int ii = 0; ii < 4; ii++) {
        int i = i0 + ty*4 + ii;
        float o[4];
#pragma unroll
        for (int jj = 0; jj < 4; jj++) o[jj] = beta*acc[ii][jj];
        if (alpha != 0.f) {
            float4 pv = *(const float4*)(P + (size_t)i*256 + j0 + tx*4);
            o[0] += alpha*pv.x; o[1] += alpha*pv.y; o[2] += alpha*pv.z; o[3] += alpha*pv.w;
        }
        if (diag != 0.f) {
#pragma unroll
            for (int jj = 0; jj < 4; jj++) if (i == j0 + tx*4 + jj) o[jj] += diag;
        }
        *(float4*)(O + (size_t)i*NQ + j0 + tx*4) = make_float4(o[0], o[1], o[2], o[3]);
    }
}

// ---------- attn3v: split-KV flash ----------
#define SMEM_A3V (4*64*68*4)
__global__ void k_attn3v(const float* __restrict__ k, const float* __restrict__ v) {
    extern __shared__ float sm[];
    float* sQt = sm;
    float* sKt = sm + 64*68;
    float* sV  = sm + 2*64*68;
    float* sP  = sm + 3*64*68;
    int bh = blockIdx.z, m0 = blockIdx.x*64, sp = blockIdx.y;
    int t = threadIdx.x, tx = t & 15, ty = t >> 4;
    for (int i = t; i < 64*16; i += 256) {
        int row = i >> 4, c = i & 15;
        float4 qv = *(const float4*)(g_qland + ((size_t)bh*MLAND + m0 + row)*DH + c*4);
        sQt[(c*4+0)*68 + row] = qv.x; sQt[(c*4+1)*68 + row] = qv.y;
        sQt[(c*4+2)*68 + row] = qv.z; sQt[(c*4+3)*68 + row] = qv.w;
    }
    float m_run[4], l_run[4], acc[4][4];
#pragma unroll
    for (int i = 0; i < 4; i++) {
        m_run[i] = -1e30f; l_run[i] = 0.f;
#pragma unroll
        for (int j = 0; j < 4; j++) acc[i][j] = 0.f;
    }
    const float* kb = k + (size_t)bh*NSEQ*DH;
    const float* vb = v + (size_t)bh*NSEQ*DH;
    int n0base = sp * (NSEQ/SPLITS);
    __syncthreads();
    for (int c0 = 0; c0 < NSEQ/SPLITS; c0 += 64) {
        int n0 = n0base + c0;
        for (int i = t; i < 64*16; i += 256) {
            int row = i >> 4, cc = i & 15;
            float4 kv = *(const float4*)(kb + (size_t)(n0+row)*DH + cc*4);
            sKt[(cc*4+0)*68 + row] = kv.x; sKt[(cc*4+1)*68 + row] = kv.y;
            sKt[(cc*4+2)*68 + row] = kv.z; sKt[(cc*4+3)*68 + row] = kv.w;
            *(float4*)(sV + row*68 + cc*4) = *(const float4*)(vb + (size_t)(n0+row)*DH + cc*4);
        }
        __syncthreads();
        float s4[4][4];
#pragma unroll
        for (int i = 0; i < 4; i++)
#pragma unroll
            for (int j = 0; j < 4; j++) s4[i][j] = 0.f;
        for (int d = 0; d < 64; d++) {
            float4 qv = *(float4*)(sQt + d*68 + ty*4);
            float4 kv = *(float4*)(sKt + d*68 + tx*4);
            float qr[4] = {qv.x,qv.y,qv.z,qv.w}, kr[4] = {kv.x,kv.y,kv.z,kv.w};
#pragma unroll
            for (int i = 0; i < 4; i++)
#pragma unroll
                for (int j = 0; j < 4; j++) s4[i][j] += qr[i]*kr[j];
        }
#pragma unroll
        for (int i = 0; i < 4; i++) {
            float mx = fmaxf(fmaxf(s4[i][0], s4[i][1]), fmaxf(s4[i][2], s4[i][3]));
#pragma unroll
            for (int o = 8; o; o >>= 1) mx = fmaxf(mx, __shfl_xor_sync(0xffffffffu, mx, o, 16));
            float mn = fmaxf(m_run[i], mx);
            float corr = __expf(m_run[i] - mn);
            m_run[i] = mn;
            float ls = 0.f;
#pragma unroll
            for (int j = 0; j < 4; j++) { s4[i][j] = __expf(s4[i][j] - mn); ls += s4[i][j]; }
#pragma unroll
            for (int o = 8; o; o >>= 1) ls += __shfl_xor_sync(0xffffffffu, ls, o, 16);
            l_run[i] = l_run[i]*corr + ls;
#pragma unroll
            for (int j = 0; j < 4; j++) acc[i][j] *= corr;
        }
#pragma unroll
        for (int j = 0; j < 4; j++)
            *(float4*)(sP + (tx*4+j)*68 + ty*4) = make_float4(s4[0][j], s4[1][j], s4[2][j], s4[3][j]);
        __syncthreads();
        for (int kk = 0; kk < 64; kk++) {
            float4 pv = *(float4*)(sP + kk*68 + ty*4);
            float4 vv = *(float4*)(sV + kk*68 + tx*4);
            float pr[4] = {pv.x,pv.y,pv.z,pv.w}, vr[4] = {vv.x,vv.y,vv.z,vv.w};
#pragma unroll
            for (int i = 0; i < 4; i++)
#pragma unroll
                for (int j = 0; j < 4; j++) acc[i][j] += pr[i]*vr[j];
        }
        __syncthreads();
    }
    float* outp = g_p3vp + (((size_t)sp*BH + bh)*MLAND + m0)*DH;
#pragma unroll
    for (int i = 0; i < 4; i++)
        *(float4*)(outp + (size_t)(ty*4+i)*DH + tx*4) =
            make_float4(acc[i][0], acc[i][1], acc[i][2], acc[i][3]);
    if (tx == 0) {
#pragma unroll
        for (int i = 0; i < 4; i++) {
            size_t mi = (((size_t)sp*BH + bh)*MLAND + m0 + ty*4 + i)*2;
            g_mlp[mi] = m_run[i]; g_mlp[mi+1] = l_run[i];
        }
    }
}

__global__ void k_combine() {
    int row = blockIdx.x, bh = blockIdx.y, d = threadIdx.x;
    float m[SPLITS], l[SPLITS];
#pragma unroll
    for (int s = 0; s < SPLITS; s++) {
        size_t mi = (((size_t)s*BH + bh)*MLAND + row)*2;
        m[s] = g_mlp[mi]; l[s] = g_mlp[mi+1];
    }
    float M = m[0];
#pragma unroll
    for (int s = 1; s < SPLITS; s++) M = fmaxf(M, m[s]);
    float L = 0.f, o = 0.f;
#pragma unroll
    for (int s = 0; s < SPLITS; s++) {
        float w = __expf(m[s] - M);
        L += l[s]*w;
        o += g_p3vp[(((size_t)s*BH + bh)*MLAND + row)*DH + d] * w;
    }
    g_p3v[((size_t)bh*MLAND + row)*DH + d] = o / L;
}

// ---------- fused1 ----------
#define SMEM_F1 ((256*68 + 32*68 + 32*264)*4)
__global__ void k_fused1(const float* __restrict__ q, const float* __restrict__ v,
                         const float* __restrict__ cw, float* __restrict__ out) {
    extern __shared__ float sm[];
    float* kl = sm;
    float* ql = sm + 256*68;
    float* ss = sm + 256*68 + 32*68;
    int bh = blockIdx.y, g0 = blockIdx.x*32, t = threadIdx.x;
    int r = t >> 3, j8 = t & 7;
    const float4* ksrc = (const float4*)(g_kland + (size_t)bh*MLAND*DH);
    for (int i = t; i < 256*16; i += 256) { int row=i>>4, c=i&15; *(float4*)(kl+row*68+c*4) = ksrc[row*16+c]; }
    const float4* qsrc = (const float4*)(q + ((size_t)bh*NSEQ + g0)*DH);
    for (int i = t; i < 32*16; i += 256)  { int row=i>>4, c=i&15; *(float4*)(ql+row*68+c*4) = qsrc[row*16+c]; }
    __syncthreads();
    float acc[32];
#pragma unroll
    for (int c = 0; c < 32; c++) acc[c] = 0.f;
    for (int kk = 0; kk < 64; kk += 4) {
        float4 qv = *(float4*)(ql + r*68 + kk);
#pragma unroll
        for (int c = 0; c < 32; c++) {
            float4 kv = *(float4*)(kl + (j8 + 8*c)*68 + kk);
            acc[c] += qv.x*kv.x + qv.y*kv.y + qv.z*kv.z + qv.w*kv.w;
        }
    }
    float mx = -1e30f;
#pragma unroll
    for (int c = 0; c < 32; c++) mx = fmaxf(mx, acc[c]);
#pragma unroll
    for (int o = 4; o; o >>= 1) mx = fmaxf(mx, __shfl_xor_sync(0xffffffffu, mx, o, 8));
    float sum = 0.f;
#pragma unroll
    for (int c = 0; c < 32; c++) { acc[c] = __expf(acc[c] - mx); sum += acc[c]; }
#pragma unroll
    for (int o = 4; o; o >>= 1) sum += __shfl_xor_sync(0xffffffffu, sum, o, 8);
    float inv = 1.f / sum;
#pragma unroll
    for (int c = 0; c < 32; c++) ss[r*264 + j8 + 8*c] = acc[c] * inv;
    __syncthreads();
    const float4* wsrc = (const float4*)(g_W + (size_t)bh*MLAND*DH);
    for (int i = t; i < 256*16; i += 256) { int row=i>>4, c=i&15; *(float4*)(kl+row*68+c*4) = wsrc[row*16+c]; }
    __syncthreads();
    float oacc[8];
#pragma unroll
    for (int c = 0; c < 8; c++) oacc[c] = 0.f;
    int col = j8*8;
    const float* srow = ss + r*264;
    for (int kk = 0; kk < 256; kk += 4) {
        float4 p4 = *(float4*)(srow + kk);
        float pk[4] = {p4.x, p4.y, p4.z, p4.w};
#pragma unroll
        for (int u = 0; u < 4; u++) {
            float4 w0 = *(float4*)(kl + (kk+u)*68 + col);
            float4 w1 = *(float4*)(kl + (kk+u)*68 + col + 4);
            oacc[0] += pk[u]*w0.x; oacc[1] += pk[u]*w0.y; oacc[2] += pk[u]*w0.z; oacc[3] += pk[u]*w0.w;
            oacc[4] += pk[u]*w1.x; oacc[5] += pk[u]*w1.y; oacc[6] += pk[u]*w1.z; oacc[7] += pk[u]*w1.w;
        }
    }
    __syncthreads();
    const float* vb = v + (size_t)bh*NSEQ*DH;
    for (int i = t; i < 64*16; i += 256) {
        int row = i >> 4, c = i & 15, gr = g0 - 16 + row;
        float4 val = make_float4(0.f, 0.f, 0.f, 0.f);
        if (gr >= 0 && gr < NSEQ) val = *(const float4*)(vb + (size_t)gr*DH + c*4);
        *(float4*)(kl + row*68 + c*4) = val;
    }
    if (t < 33) ql[t] = cw[(bh & 7)*33 + t];
    __syncthreads();
    float res[8];
#pragma unroll
    for (int c = 0; c < 8; c++) res[c] = 0.f;
#pragma unroll
    for (int tt = 0; tt < 33; tt++) {
        float w = ql[tt];
        float4 v0 = *(float4*)(kl + (r + tt)*68 + col);
        float4 v1 = *(float4*)(kl + (r + tt)*68 + col + 4);
        res[0] += w*v0.x; res[1] += w*v0.y; res[2] += w*v0.z; res[3] += w*v0.w;
        res[4] += w*v1.x; res[5] += w*v1.y; res[6] += w*v1.z; res[7] += w*v1.w;
    }
    float* ob = out + ((size_t)bh*NSEQ + g0 + r)*DH + col;
    *(float4*)ob       = make_float4(oacc[0]+res[0], oacc[1]+res[1], oacc[2]+res[2], oacc[3]+res[3]);
    *(float4*)(ob + 4) = make_float4(oacc[4]+res[4], oacc[5]+res[5], oacc[6]+res[6], oacc[7]+res[7]);
}

// ---------- launcher ----------
extern "C" void kernel_launch(void* const* d_in, const int* in_sizes, int n_in,
                              void* d_out, int out_size) {
    (void)in_sizes; (void)n_in; (void)out_size;
    const float* q  = (const float*)d_in[0];
    const float* k  = (const float*)d_in[1];
    const float* v  = (const float*)d_in[2];
    const float* cw = (const float*)d_in[3];
    float* out = (float*)d_out;

    cudaFuncSetAttribute(k_attn2,  cudaFuncAttributeMaxDynamicSharedMemorySize, SMEM_ATTN2);
    cudaFuncSetAttribute(k_attn3v, cudaFuncAttributeMaxDynamicSharedMemorySize, SMEM_A3V);
    cudaFuncSetAttribute(k_fused1, cudaFuncAttributeMaxDynamicSharedMemorySize, SMEM_F1);

    float *pool, *p3v, *W;
    cudaGetSymbolAddress((void**)&pool, g_pool);
    cudaGetSymbolAddress((void**)&p3v, g_p3v);
    cudaGetSymbolAddress((void**)&W, g_W);
    const size_t S = (size_t)BH*MMSZ;
    auto Pp = [&](int s) { return pool + (size_t)s*S; };

    k_landmarks<<<dim3(MLAND, BH, 2), 64>>>(q, k);
    k_attn2<<<dim3(8, BH), 256, SMEM_ATTN2>>>();
    k_colrow<<<BH, 256>>>();
    k_attn3v<<<dim3(4, SPLITS, BH), 256, SMEM_A3V>>>(k, v);
    k_combine<<<dim3(MLAND, BH), 64>>>();

    dim3 mg(4, 2, BH);
    auto TM = [&](int mA, int mB, const float* P, float* C, float* CT,
                  float al, float be, float dg, int sc) {
        k_tmma32<<<mg, 256>>>(Pp(mA), Pp(mB), P, C, CT, al, be, dg, sc);
    };
    // iter 1 (z0 = s*X^T folded into operands)
    TM(PX,  PX,  nullptr, Pp(PA), Pp(PAT), 0.f,    1.f,   0.f,   1); // A = s*X@X^T
    TM(PA,  PAT, Pp(PA),  nullptr, Pp(PTT), 7.f,  -1.f,   0.f,   0); // T^T = (7A - A@A)^T
    TM(PA,  PTT, Pp(PA),  nullptr, Pp(PVT), -3.75f, 0.25f, 3.25f, 0); // V^T
    TM(PXT, PVT, nullptr, Pp(PZ0), Pp(PZ0T), 0.f,  1.f,   0.f,   1); // z1 = s*X^T@V
    int zc = PZ0, zct = PZ0T, zn = PZ1, znt = PZ1T;
    for (int it = 2; it <= 4; it++) {
        TM(PX, zct, nullptr, Pp(PA), Pp(PAT), 0.f,    1.f,   0.f,   0);
        TM(PA, PAT, Pp(PA),  nullptr, Pp(PTT), 7.f,  -1.f,   0.f,   0);
        TM(PA, PTT, Pp(PA),  nullptr, Pp(PVT), -3.75f, 0.25f, 3.25f, 0);
        if (it < 4) {
            TM(zc, PVT, nullptr, Pp(zn), Pp(znt), 0.f, 1.f, 0.f, 0);
            int x = zc; zc = zn; zn = x; x = zct; zct = znt; znt = x;
        } else {
            TM(zc, PVT, nullptr, Pp(PZ1), nullptr, 0.f, 1.f, 0.f, 0);  // z4 rows only
        }
    }
    // iters 5,6 exact fp32 (firewall), then W
    dim3 gg(4, 4, BH);
    float *X = Pp(PX), *A = Pp(PA), *T = Pp(PTT), *V = Pp(PVT);
    float *zi = Pp(PZ1), *zo = Pp(PZ0);
    for (int it = 5; it <= 6; it++) {
        k_gemm2<256><<<gg, 256>>>(X,  zi, A, 0.f, 1.f, 0.f);
        k_gemm2<256><<<gg, 256>>>(A,  A,  T, 7.f, -1.f, 0.f);
        k_gemm2<256><<<gg, 256>>>(A,  T,  V, -3.75f, 0.25f, 3.25f);
        k_gemm2<256><<<gg, 256>>>(zi, V,  zo, 0.f, 1.f, 0.f);
        float* tp = zi; zi = zo; zo = tp;
    }
    k_gemm2<64><<<dim3(1, 4, BH), 256>>>(zi, p3v, W, 0.f, 1.f, 0.f);
    k_fused1<<<dim3(256, BH), 256, SMEM_F1>>>(q, v, cw, out);
}

// round 11
// speedup vs baseline: 1.0467x; 1.0154x over previous
#include <cuda_runtime.h>
#include <cstdint>

#define BH     16
#define NSEQ   8192
#define DH     64
#define MLAND  256
#define MMSZ   (MLAND*MLAND)
#define SPLITS 8

// fp32 matrix pool slots
#define PX   0
#define PXT  1
#define PA   2
#define PAT  3
#define PTT  4
#define PVT  5
#define PZ0  6
#define PZ0T 7
#define PZ1  8
#define PZ1T 9
__device__ float g_pool[10ll*BH*MMSZ];
__device__ float g_qland[BH*MLAND*DH];
__device__ float g_kland[BH*MLAND*DH];
__device__ float g_p3v[BH*MLAND*DH];
__device__ float g_p3vp[(size_t)SPLITS*BH*MLAND*DH];
__device__ float g_mlp[(size_t)SPLITS*BH*MLAND*2];
__device__ float g_W[BH*MLAND*DH];
__device__ int   g_maxcs, g_maxrs;

__device__ __forceinline__ float tf32r(float x) {
    uint32_t u;
    asm("cvt.rna.tf32.f32 %0, %1;" : "=r"(u) : "f"(x));
    return __uint_as_float(u);
}
#define MMA_TF32(c, a0, a1, a2, a3, b0, b1) \
    asm volatile("mma.sync.aligned.m16n8k8.row.col.f32.tf32.tf32.f32 " \
        "{%0,%1,%2,%3}, {%4,%5,%6,%7}, {%8,%9}, {%0,%1,%2,%3};" \
        : "+f"((c)[0]), "+f"((c)[1]), "+f"((c)[2]), "+f"((c)[3]) \
        : "r"(a0), "r"(a1), "r"(a2), "r"(a3), "r"(b0), "r"(b1))

// ---------- kernel 1: landmarks ----------
__global__ void k_landmarks(const float* __restrict__ q, const float* __restrict__ k) {
    int m = blockIdx.x, bh = blockIdx.y;
    const float* src = blockIdx.z ? k : q;
    float* dst = blockIdx.z ? g_kland : g_qland;
    int j = threadIdx.x;
    const float* p = src + ((size_t)bh*NSEQ + (size_t)m*32)*DH + j;
    float s = 0.f;
#pragma unroll
    for (int r = 0; r < 32; r++) s += p[r*DH];
    dst[(bh*MLAND + m)*DH + j] = s * (1.f/32.f);
    if (blockIdx.z == 0 && m == 0 && bh == 0 && j == 0) { g_maxcs = 0; g_maxrs = 0; }
}

// ---------- kernel 2: attn2 -> X, XT (fp32) ----------
#define SMEM_ATTN2 ((256*68 + 32*68)*4)
__global__ void k_attn2() {
    extern __shared__ float sm[];
    float* kl = sm;
    float* ql = sm + 256*68;
    int bh = blockIdx.y, r0 = blockIdx.x*32, t = threadIdx.x;
    const float4* ks = (const float4*)(g_kland + (size_t)bh*MLAND*DH);
    for (int i = t; i < 256*16; i += 256) { int row=i>>4, c=i&15; *(float4*)(kl+row*68+c*4) = ks[row*16+c]; }
    const float4* qs = (const float4*)(g_qland + ((size_t)bh*MLAND + r0)*DH);
    for (int i = t; i < 32*16; i += 256)  { int row=i>>4, c=i&15; *(float4*)(ql+row*68+c*4) = qs[row*16+c]; }
    __syncthreads();
    int r = t >> 3, j8 = t & 7;
    float acc[32];
#pragma unroll
    for (int c = 0; c < 32; c++) acc[c] = 0.f;
    for (int kk = 0; kk < 64; kk += 4) {
        float4 qv = *(float4*)(ql + r*68 + kk);
#pragma unroll
        for (int c = 0; c < 32; c++) {
            float4 kv = *(float4*)(kl + (j8 + 8*c)*68 + kk);
            acc[c] += qv.x*kv.x + qv.y*kv.y + qv.z*kv.z + qv.w*kv.w;
        }
    }
    float mx = -1e30f;
#pragma unroll
    for (int c = 0; c < 32; c++) mx = fmaxf(mx, acc[c]);
#pragma unroll
    for (int o = 4; o; o >>= 1) mx = fmaxf(mx, __shfl_xor_sync(0xffffffffu, mx, o, 8));
    float sum = 0.f;
#pragma unroll
    for (int c = 0; c < 32; c++) { acc[c] = __expf(acc[c] - mx); sum += acc[c]; }
#pragma unroll
    for (int o = 4; o; o >>= 1) sum += __shfl_xor_sync(0xffffffffu, sum, o, 8);
    float inv = 1.f / sum;
    int row = r0 + r;
    float* X  = g_pool + ((size_t)PX*BH + bh)*MMSZ;
    float* XT = g_pool + ((size_t)PXT*BH + bh)*MMSZ;
#pragma unroll
    for (int c = 0; c < 32; c++) {
        float vv = acc[c] * inv;
        int col = j8 + 8*c;
        X[(size_t)row*MLAND + col] = vv;
        XT[(size_t)col*MLAND + row] = vv;
    }
}

// ---------- kernel 3: max col/row sums ----------
__global__ void k_colrow() {
    int bh = blockIdx.x, t = threadIdx.x;
    const float* x = g_pool + ((size_t)PX*BH + bh)*MMSZ;
    float cs = 0.f, rs = 0.f;
    for (int i = 0; i < 256; i++) cs += x[i*256 + t];
    for (int j = 0; j < 256; j++) rs += x[t*256 + j];
#pragma unroll
    for (int o = 16; o; o >>= 1) {
        cs = fmaxf(cs, __shfl_xor_sync(0xffffffffu, cs, o));
        rs = fmaxf(rs, __shfl_xor_sync(0xffffffffu, rs, o));
    }
    __shared__ float sc[8], sr[8];
    if ((t & 31) == 0) { sc[t>>5] = cs; sr[t>>5] = rs; }
    __syncthreads();
    if (t == 0) {
        float mc = sc[0], mr = sr[0];
        for (int w = 1; w < 8; w++) { mc = fmaxf(mc, sc[w]); mr = fmaxf(mr, sr[w]); }
        atomicMax(&g_maxcs, __float_as_int(mc));
        atomicMax(&g_maxrs, __float_as_int(mr));
    }
}

// ---------- tf32 tensor-core GEMM: C = alpha*P + beta*(A @ Bop^T) + diag*I ----------
// 64x64 block tile, grid (4, 4, BH) = 256 blocks. 256 thr = 8 warps (2M x 4N), warp 32x16.
__global__ void __launch_bounds__(256) k_tmma32(
    const float* __restrict__ Ag, const float* __restrict__ Bg, const float* __restrict__ Pg,
    float* __restrict__ Cg, float* __restrict__ CTg,
    float alpha, float beta, float diag, int scaled)
{
    __shared__ __align__(16) float sA[2][64][20];
    __shared__ __align__(16) float sB[2][64][20];
    int bh = blockIdx.z;
    int row0 = blockIdx.y*64, col0 = blockIdx.x*64;
    int t = threadIdx.x, lane = t & 31, w = t >> 5;
    int wm = w >> 2, wn = w & 3;           // warp tile: rows wm*32, cols wn*16
    int gid = lane >> 2, tig = lane & 3;
    const float* Ab = Ag + (size_t)bh*MMSZ;
    const float* Bb = Bg + (size_t)bh*MMSZ;
    int lr = t >> 2, lc = (t & 3)*4;       // loader: row 0..63, col 0/4/8/12 within 16-wide chunk
    const float* gA = Ab + (size_t)(row0 + lr)*MLAND + lc;
    const float* gB = Bb + (size_t)(col0 + lr)*MLAND + lc;

    float4 av = *(const float4*)gA;
    float4 bv = *(const float4*)gB;
    auto stage = [&](int buf, float4 a, float4 b) {
        *(float4*)&sA[buf][lr][lc] = make_float4(tf32r(a.x), tf32r(a.y), tf32r(a.z), tf32r(a.w));
        *(float4*)&sB[buf][lr][lc] = make_float4(tf32r(b.x), tf32r(b.y), tf32r(b.z), tf32r(b.w));
    };
    stage(0, av, bv);
    __syncthreads();

    float acc[2][2][4];
#pragma unroll
    for (int i = 0; i < 2; i++)
#pragma unroll
        for (int j = 0; j < 2; j++)
#pragma unroll
            for (int c = 0; c < 4; c++) acc[i][j][c] = 0.f;

    for (int ks = 0; ks < 16; ks++) {
        int cur = ks & 1;
        if (ks < 15) {
            av = *(const float4*)(gA + (ks+1)*16);
            bv = *(const float4*)(gB + (ks+1)*16);
        }
#pragma unroll
        for (int kh = 0; kh < 2; kh++) {
            int kb = kh*8 + tig;
            uint32_t af[2][4], bfr[2][2];
#pragma unroll
            for (int mt = 0; mt < 2; mt++) {
                int rr = wm*32 + mt*16 + gid;
                af[mt][0] = __float_as_uint(sA[cur][rr    ][kb]);
                af[mt][1] = __float_as_uint(sA[cur][rr + 8][kb]);
                af[mt][2] = __float_as_uint(sA[cur][rr    ][kb + 4]);
                af[mt][3] = __float_as_uint(sA[cur][rr + 8][kb + 4]);
            }
#pragma unroll
            for (int nt = 0; nt < 2; nt++) {
                int cc = wn*16 + nt*8 + gid;
                bfr[nt][0] = __float_as_uint(sB[cur][cc][kb]);
                bfr[nt][1] = __float_as_uint(sB[cur][cc][kb + 4]);
            }
#pragma unroll
            for (int mt = 0; mt < 2; mt++)
#pragma unroll
                for (int nt = 0; nt < 2; nt++)
                    MMA_TF32(acc[mt][nt], af[mt][0], af[mt][1], af[mt][2], af[mt][3],
                             bfr[nt][0], bfr[nt][1]);
        }
        if (ks < 15) {
            stage(cur ^ 1, av, bv);
            __syncthreads();
        }
    }

    float be = beta;
    if (scaled) be *= 1.f / (__int_as_float(g_maxcs) * __int_as_float(g_maxrs));
    const float* Pb = Pg ? Pg + (size_t)bh*MMSZ : (const float*)0;
    float* Cp  = Cg  ? Cg  + (size_t)bh*MMSZ : (float*)0;
    float* CTp = CTg ? CTg + (size_t)bh*MMSZ : (float*)0;
#pragma unroll
    for (int mt = 0; mt < 2; mt++)
#pragma unroll
        for (int nt = 0; nt < 2; nt++) {
            int gcol = col0 + wn*16 + nt*8 + 2*tig;
#pragma unroll
            for (int half = 0; half < 2; half++) {
                int grow = row0 + wm*32 + mt*16 + gid + half*8;
                float o0 = be * acc[mt][nt][2*half + 0];
                float o1 = be * acc[mt][nt][2*half + 1];
                if (Pb) {
                    float2 pv = *(const float2*)(Pb + (size_t)grow*MLAND + gcol);
                    o0 += alpha * pv.x;
                    o1 += alpha * pv.y;
                }
                if (diag != 0.f) {
                    if (grow == gcol)     o0 += diag;
                    if (grow == gcol + 1) o1 += diag;
                }
                if (Cp) *(float2*)(Cp + (size_t)grow*MLAND + gcol) = make_float2(o0, o1);
                if (CTp) {
                    CTp[(size_t)gcol*MLAND + grow]     = o0;
                    CTp[(size_t)(gcol+1)*MLAND + grow] = o1;
                }
            }
        }
}

// ---------- fp32 double-buffered SGEMM (iters 5,6 + W) ----------
template<int NQ>
__global__ void k_gemm2(const float* __restrict__ Pg, const float* __restrict__ Qg,
                        float* __restrict__ Og, float alpha, float beta, float diag) {
    __shared__ float sA[2][16][68];
    __shared__ float sB[2][16][68];
    int bh = blockIdx.z;
    const float* P = Pg + (size_t)bh*MMSZ;
    const float* Q = Qg + (size_t)bh*256*NQ;
    float*       O = Og + (size_t)bh*256*NQ;
    int i0 = blockIdx.y*64, j0 = blockIdx.x*64;
    int t = threadIdx.x, tx = t & 15, ty = t >> 4;
    int la_i = t >> 2, la_k = (t & 3)*4;
    int lb_k = t >> 4, lb_j = (t & 15)*4;
    const float* pA = P + (size_t)(i0 + la_i)*256 + la_k;
    const float* pB = Q + (size_t)lb_k*NQ + j0 + lb_j;
    float4 av = *(const float4*)pA;
    float4 bv = *(const float4*)pB;
    sA[0][la_k  ][la_i] = av.x; sA[0][la_k+1][la_i] = av.y;
    sA[0][la_k+2][la_i] = av.z; sA[0][la_k+3][la_i] = av.w;
    *(float4*)&sB[0][lb_k][lb_j] = bv;
    __syncthreads();
    float acc[4][4];
#pragma unroll
    for (int a = 0; a < 4; a++)
#pragma unroll
        for (int b = 0; b < 4; b++) acc[a][b] = 0.f;
    for (int s = 0; s < 16; s++) {
        int cur = s & 1;
        if (s < 15) {
            av = *(const float4*)(pA + (s+1)*16);
            bv = *(const float4*)(pB + (size_t)(s+1)*16*NQ);
        }
#pragma unroll
        for (int k = 0; k < 16; k++) {
            float4 a = *(float4*)&sA[cur][k][ty*4];
            float4 b = *(float4*)&sB[cur][k][tx*4];
            float ar[4] = {a.x,a.y,a.z,a.w}, br[4] = {b.x,b.y,b.z,b.w};
#pragma unroll
            for (int ii = 0; ii < 4; ii++)
#pragma unroll
                for (int jj = 0; jj < 4; jj++) acc[ii][jj] += ar[ii]*br[jj];
        }
        if (s < 15) {
            int nxt = cur ^ 1;
            sA[nxt][la_k  ][la_i] = av.x; sA[nxt][la_k+1][la_i] = av.y;
            sA[nxt][la_k+2][la_i] = av.z; sA[nxt][la_k+3][la_i] = av.w;
            *(float4*)&sB[nxt][lb_k][lb_j] = bv;
            __syncthreads();
        }
    }
#pragma unroll
    for (int ii = 0; ii < 4; ii++) {
        int i = i0 + ty*4 + ii;
        float o[4];
#pragma unroll
        for (int jj = 0; jj < 4; jj++) o[jj] = beta*acc[ii][jj];
        if (alpha != 0.f) {
            float4 pv = *(const float4*)(P + (size_t)i*256 + j0 + tx*4);
            o[0] += alpha*pv.x; o[1] += alpha*pv.y; o[2] += alpha*pv.z; o[3] += alpha*pv.w;
        }
        if (diag != 0.f) {
#pragma unroll
            for (int jj = 0; jj < 4; jj++) if (i == j0 + tx*4 + jj) o[jj] += diag;
        }
        *(float4*)(O + (size_t)i*NQ + j0 + tx*4) = make_float4(o[0], o[1], o[2], o[3]);
    }
}

// ---------- attn3v: split-KV flash ----------
#define SMEM_A3V (4*64*68*4)
__global__ void k_attn3v(const float* __restrict__ k, const float* __restrict__ v) {
    extern __shared__ float sm[];
    float* sQt = sm;
    float* sKt = sm + 64*68;
    float* sV  = sm + 2*64*68;
    float* sP  = sm + 3*64*68;
    int bh = blockIdx.z, m0 = blockIdx.x*64, sp = blockIdx.y;
    int t = threadIdx.x, tx = t & 15, ty = t >> 4;
    for (int i = t; i < 64*16; i += 256) {
        int row = i >> 4, c = i & 15;
        float4 qv = *(const float4*)(g_qland + ((size_t)bh*MLAND + m0 + row)*DH + c*4);
        sQt[(c*4+0)*68 + row] = qv.x; sQt[(c*4+1)*68 + row] = qv.y;
        sQt[(c*4+2)*68 + row] = qv.z; sQt[(c*4+3)*68 + row] = qv.w;
    }
    float m_run[4], l_run[4], acc[4][4];
#pragma unroll
    for (int i = 0; i < 4; i++) {
        m_run[i] = -1e30f; l_run[i] = 0.f;
#pragma unroll
        for (int j = 0; j < 4; j++) acc[i][j] = 0.f;
    }
    const float* kb = k + (size_t)bh*NSEQ*DH;
    const float* vb = v + (size_t)bh*NSEQ*DH;
    int n0base = sp * (NSEQ/SPLITS);
    __syncthreads();
    for (int c0 = 0; c0 < NSEQ/SPLITS; c0 += 64) {
        int n0 = n0base + c0;
        for (int i = t; i < 64*16; i += 256) {
            int row = i >> 4, cc = i & 15;
            float4 kv = *(const float4*)(kb + (size_t)(n0+row)*DH + cc*4);
            sKt[(cc*4+0)*68 + row] = kv.x; sKt[(cc*4+1)*68 + row] = kv.y;
            sKt[(cc*4+2)*68 + row] = kv.z; sKt[(cc*4+3)*68 + row] = kv.w;
            *(float4*)(sV + row*68 + cc*4) = *(const float4*)(vb + (size_t)(n0+row)*DH + cc*4);
        }
        __syncthreads();
        float s4[4][4];
#pragma unroll
        for (int i = 0; i < 4; i++)
#pragma unroll
            for (int j = 0; j < 4; j++) s4[i][j] = 0.f;
        for (int d = 0; d < 64; d++) {
            float4 qv = *(float4*)(sQt + d*68 + ty*4);
            float4 kv = *(float4*)(sKt + d*68 + tx*4);
            float qr[4] = {qv.x,qv.y,qv.z,qv.w}, kr[4] = {kv.x,kv.y,kv.z,kv.w};
#pragma unroll
            for (int i = 0; i < 4; i++)
#pragma unroll
                for (int j = 0; j < 4; j++) s4[i][j] += qr[i]*kr[j];
        }
#pragma unroll
        for (int i = 0; i < 4; i++) {
            float mx = fmaxf(fmaxf(s4[i][0], s4[i][1]), fmaxf(s4[i][2], s4[i][3]));
#pragma unroll
            for (int o = 8; o; o >>= 1) mx = fmaxf(mx, __shfl_xor_sync(0xffffffffu, mx, o, 16));
            float mn = fmaxf(m_run[i], mx);
            float corr = __expf(m_run[i] - mn);
            m_run[i] = mn;
            float ls = 0.f;
#pragma unroll
            for (int j = 0; j < 4; j++) { s4[i][j] = __expf(s4[i][j] - mn); ls += s4[i][j]; }
#pragma unroll
            for (int o = 8; o; o >>= 1) ls += __shfl_xor_sync(0xffffffffu, ls, o, 16);
            l_run[i] = l_run[i]*corr + ls;
#pragma unroll
            for (int j = 0; j < 4; j++) acc[i][j] *= corr;
        }
#pragma unroll
        for (int j = 0; j < 4; j++)
            *(float4*)(sP + (tx*4+j)*68 + ty*4) = make_float4(s4[0][j], s4[1][j], s4[2][j], s4[3][j]);
        __syncthreads();
        for (int kk = 0; kk < 64; kk++) {
            float4 pv = *(float4*)(sP + kk*68 + ty*4);
            float4 vv = *(float4*)(sV + kk*68 + tx*4);
            float pr[4] = {pv.x,pv.y,pv.z,pv.w}, vr[4] = {vv.x,vv.y,vv.z,vv.w};
#pragma unroll
            for (int i = 0; i < 4; i++)
#pragma unroll
                for (int j = 0; j < 4; j++) acc[i][j] += pr[i]*vr[j];
        }
        __syncthreads();
    }
    float* outp = g_p3vp + (((size_t)sp*BH + bh)*MLAND + m0)*DH;
#pragma unroll
    for (int i = 0; i < 4; i++)
        *(float4*)(outp + (size_t)(ty*4+i)*DH + tx*4) =
            make_float4(acc[i][0], acc[i][1], acc[i][2], acc[i][3]);
    if (tx == 0) {
#pragma unroll
        for (int i = 0; i < 4; i++) {
            size_t mi = (((size_t)sp*BH + bh)*MLAND + m0 + ty*4 + i)*2;
            g_mlp[mi] = m_run[i]; g_mlp[mi+1] = l_run[i];
        }
    }
}

__global__ void k_combine() {
    int row = blockIdx.x, bh = blockIdx.y, d = threadIdx.x;
    float m[SPLITS], l[SPLITS];
#pragma unroll
    for (int s = 0; s < SPLITS; s++) {
        size_t mi = (((size_t)s*BH + bh)*MLAND + row)*2;
        m[s] = g_mlp[mi]; l[s] = g_mlp[mi+1];
    }
    float M = m[0];
#pragma unroll
    for (int s = 1; s < SPLITS; s++) M = fmaxf(M, m[s]);
    float L = 0.f, o = 0.f;
#pragma unroll
    for (int s = 0; s < SPLITS; s++) {
        float w = __expf(m[s] - M);
        L += l[s]*w;
        o += g_p3vp[(((size_t)s*BH + bh)*MLAND + row)*DH + d] * w;
    }
    g_p3v[((size_t)bh*MLAND + row)*DH + d] = o / L;
}

// ---------- fused1 ----------
#define SMEM_F1 ((256*68 + 32*68 + 32*264)*4)
__global__ void k_fused1(const float* __restrict__ q, const float* __restrict__ v,
                         const float* __restrict__ cw, float* __restrict__ out) {
    extern __shared__ float sm[];
    float* kl = sm;
    float* ql = sm + 256*68;
    float* ss = sm + 256*68 + 32*68;
    int bh = blockIdx.y, g0 = blockIdx.x*32, t = threadIdx.x;
    int r = t >> 3, j8 = t & 7;
    const float4* ksrc = (const float4*)(g_kland + (size_t)bh*MLAND*DH);
    for (int i = t; i < 256*16; i += 256) { int row=i>>4, c=i&15; *(float4*)(kl+row*68+c*4) = ksrc[row*16+c]; }
    const float4* qsrc = (const float4*)(q + ((size_t)bh*NSEQ + g0)*DH);
    for (int i = t; i < 32*16; i += 256)  { int row=i>>4, c=i&15; *(float4*)(ql+row*68+c*4) = qsrc[row*16+c]; }
    __syncthreads();
    float acc[32];
#pragma unroll
    for (int c = 0; c < 32; c++) acc[c] = 0.f;
    for (int kk = 0; kk < 64; kk += 4) {
        float4 qv = *(float4*)(ql + r*68 + kk);
#pragma unroll
        for (int c = 0; c < 32; c++) {
            float4 kv = *(float4*)(kl + (j8 + 8*c)*68 + kk);
            acc[c] += qv.x*kv.x + qv.y*kv.y + qv.z*kv.z + qv.w*kv.w;
        }
    }
    float mx = -1e30f;
#pragma unroll
    for (int c = 0; c < 32; c++) mx = fmaxf(mx, acc[c]);
#pragma unroll
    for (int o = 4; o; o >>= 1) mx = fmaxf(mx, __shfl_xor_sync(0xffffffffu, mx, o, 8));
    float sum = 0.f;
#pragma unroll
    for (int c = 0; c < 32; c++) { acc[c] = __expf(acc[c] - mx); sum += acc[c]; }
#pragma unroll
    for (int o = 4; o; o >>= 1) sum += __shfl_xor_sync(0xffffffffu, sum, o, 8);
    float inv = 1.f / sum;
#pragma unroll
    for (int c = 0; c < 32; c++) ss[r*264 + j8 + 8*c] = acc[c] * inv;
    __syncthreads();
    const float4* wsrc = (const float4*)(g_W + (size_t)bh*MLAND*DH);
    for (int i = t; i < 256*16; i += 256) { int row=i>>4, c=i&15; *(float4*)(kl+row*68+c*4) = wsrc[row*16+c]; }
    __syncthreads();
    float oacc[8];
#pragma unroll
    for (int c = 0; c < 8; c++) oacc[c] = 0.f;
    int col = j8*8;
    const float* srow = ss + r*264;
    for (int kk = 0; kk < 256; kk += 4) {
        float4 p4 = *(float4*)(srow + kk);
        float pk[4] = {p4.x, p4.y, p4.z, p4.w};
#pragma unroll
        for (int u = 0; u < 4; u++) {
            float4 w0 = *(float4*)(kl + (kk+u)*68 + col);
            float4 w1 = *(float4*)(kl + (kk+u)*68 + col + 4);
            oacc[0] += pk[u]*w0.x; oacc[1] += pk[u]*w0.y; oacc[2] += pk[u]*w0.z; oacc[3] += pk[u]*w0.w;
            oacc[4] += pk[u]*w1.x; oacc[5] += pk[u]*w1.y; oacc[6] += pk[u]*w1.z; oacc[7] += pk[u]*w1.w;
        }
    }
    __syncthreads();
    const float* vb = v + (size_t)bh*NSEQ*DH;
    for (int i = t; i < 64*16; i += 256) {
        int row = i >> 4, c = i & 15, gr = g0 - 16 + row;
        float4 val = make_float4(0.f, 0.f, 0.f, 0.f);
        if (gr >= 0 && gr < NSEQ) val = *(const float4*)(vb + (size_t)gr*DH + c*4);
        *(float4*)(kl + row*68 + c*4) = val;
    }
    if (t < 33) ql[t] = cw[(bh & 7)*33 + t];
    __syncthreads();
    float res[8];
#pragma unroll
    for (int c = 0; c < 8; c++) res[c] = 0.f;
#pragma unroll
    for (int tt = 0; tt < 33; tt++) {
        float w = ql[tt];
        float4 v0 = *(float4*)(kl + (r + tt)*68 + col);
        float4 v1 = *(float4*)(kl + (r + tt)*68 + col + 4);
        res[0] += w*v0.x; res[1] += w*v0.y; res[2] += w*v0.z; res[3] += w*v0.w;
        res[4] += w*v1.x; res[5] += w*v1.y; res[6] += w*v1.z; res[7] += w*v1.w;
    }
    float* ob = out + ((size_t)bh*NSEQ + g0 + r)*DH + col;
    *(float4*)ob       = make_float4(oacc[0]+res[0], oacc[1]+res[1], oacc[2]+res[2], oacc[3]+res[3]);
    *(float4*)(ob + 4) = make_float4(oacc[4]+res[4], oacc[5]+res[5], oacc[6]+res[6], oacc[7]+res[7]);
}

// ---------- launcher ----------
extern "C" void kernel_launch(void* const* d_in, const int* in_sizes, int n_in,
                              void* d_out, int out_size) {
    (void)in_sizes; (void)n_in; (void)out_size;
    const float* q  = (const float*)d_in[0];
    const float* k  = (const float*)d_in[1];
    const float* v  = (const float*)d_in[2];
    const float* cw = (const float*)d_in[3];
    float* out = (float*)d_out;

    cudaFuncSetAttribute(k_attn2,  cudaFuncAttributeMaxDynamicSharedMemorySize, SMEM_ATTN2);
    cudaFuncSetAttribute(k_attn3v, cudaFuncAttributeMaxDynamicSharedMemorySize, SMEM_A3V);
    cudaFuncSetAttribute(k_fused1, cudaFuncAttributeMaxDynamicSharedMemorySize, SMEM_F1);

    float *pool, *p3v, *W;
    cudaGetSymbolAddress((void**)&pool, g_pool);
    cudaGetSymbolAddress((void**)&p3v, g_p3v);
    cudaGetSymbolAddress((void**)&W, g_W);
    const size_t S = (size_t)BH*MMSZ;
    auto Pp = [&](int s) { return pool + (size_t)s*S; };

    k_landmarks<<<dim3(MLAND, BH, 2), 64>>>(q, k);
    k_attn2<<<dim3(8, BH), 256, SMEM_ATTN2>>>();
    k_colrow<<<BH, 256>>>();
    k_attn3v<<<dim3(4, SPLITS, BH), 256, SMEM_A3V>>>(k, v);
    k_combine<<<dim3(MLAND, BH), 64>>>();

    dim3 mg(4, 4, BH);
    auto TM = [&](int mA, int mB, const float* P, float* C, float* CT,
                  float al, float be, float dg, int sc) {
        k_tmma32<<<mg, 256>>>(Pp(mA), Pp(mB), P, C, CT, al, be, dg, sc);
    };
    // iter 1 (z0 = s*X^T folded into operands)
    TM(PX,  PX,  nullptr, Pp(PA), Pp(PAT), 0.f,    1.f,   0.f,   1); // A = s*X@X^T
    TM(PA,  PAT, Pp(PA),  nullptr, Pp(PTT), 7.f,  -1.f,   0.f,   0); // T^T = (7A - A@A)^T
    TM(PA,  PTT, Pp(PA),  nullptr, Pp(PVT), -3.75f, 0.25f, 3.25f, 0); // V^T
    TM(PXT, PVT, nullptr, Pp(PZ0), Pp(PZ0T), 0.f,  1.f,   0.f,   1); // z1 = s*X^T@V
    int zc = PZ0, zct = PZ0T, zn = PZ1, znt = PZ1T;
    for (int it = 2; it <= 4; it++) {
        TM(PX, zct, nullptr, Pp(PA), Pp(PAT), 0.f,    1.f,   0.f,   0);
        TM(PA, PAT, Pp(PA),  nullptr, Pp(PTT), 7.f,  -1.f,   0.f,   0);
        TM(PA, PTT, Pp(PA),  nullptr, Pp(PVT), -3.75f, 0.25f, 3.25f, 0);
        if (it < 4) {
            TM(zc, PVT, nullptr, Pp(zn), Pp(znt), 0.f, 1.f, 0.f, 0);
            int x = zc; zc = zn; zn = x; x = zct; zct = znt; znt = x;
        } else {
            TM(zc, PVT, nullptr, Pp(PZ1), nullptr, 0.f, 1.f, 0.f, 0);  // z4 rows only
        }
    }
    // iters 5,6 exact fp32 (firewall), then W
    dim3 gg(4, 4, BH);
    float *X = Pp(PX), *A = Pp(PA), *T = Pp(PTT), *V = Pp(PVT);
    float *zi = Pp(PZ1), *zo = Pp(PZ0);
    for (int it = 5; it <= 6; it++) {
        k_gemm2<256><<<gg, 256>>>(X,  zi, A, 0.f, 1.f, 0.f);
        k_gemm2<256><<<gg, 256>>>(A,  A,  T, 7.f, -1.f, 0.f);
        k_gemm2<256><<<gg, 256>>>(A,  T,  V, -3.75f, 0.25f, 3.25f);
        k_gemm2<256><<<gg, 256>>>(zi, V,  zo, 0.f, 1.f, 0.f);
        float* tp = zi; zi = zo; zo = tp;
    }
    k_gemm2<64><<<dim3(1, 4, BH), 256>>>(zi, p3v, W, 0.f, 1.f, 0.f);
    k_fused1<<<dim3(256, BH), 256, SMEM_F1>>>(q, v, cw, out);
}